// round 5
// baseline (speedup 1.0000x reference)
#include <cuda_runtime.h>
#include <cstdint>

// ===================== problem sizes =====================
#define TOKENS 8192      // B*S = 4*2048
#define HID    2048
#define IDIM   8192

// ===================== scratch (device globals) =====================
__device__ float g_Y  [TOKENS * HID];          // 64 MB  LN output (tf32, K-permuted)
__device__ float g_W1t[2 * IDIM * HID];        // 128 MB W1^T [16384][2048] (tf32, K-perm)
__device__ float g_W2t[HID * IDIM];            // 64 MB  W2^T [2048][8192]  (tf32, K-perm)
__device__ float g_Z  [TOKENS * IDIM];         // 256 MB GeGLU output (tf32, K-perm)

// ===================== helpers =====================
__device__ __forceinline__ uint32_t smem_u32(const void* p) {
    uint32_t a;
    asm("{ .reg .u64 t; cvta.to.shared.u64 t, %1; cvt.u32.u64 %0, t; }" : "=r"(a) : "l"(p));
    return a;
}
__device__ __forceinline__ float rna_tf32(float f) {
    uint32_t u;
    asm("cvt.rna.tf32.f32 %0, %1;" : "=r"(u) : "f"(f));
    return __uint_as_float(u);
}
__device__ __forceinline__ void cp_async16(uint32_t dst, const void* src) {
    asm volatile("cp.async.cg.shared.global [%0], [%1], 16;" :: "r"(dst), "l"(src) : "memory");
}
__device__ __forceinline__ void cp_commit() {
    asm volatile("cp.async.commit_group;" ::: "memory");
}
template <int N>
__device__ __forceinline__ void cp_wait() {
    asm volatile("cp.async.wait_group %0;" :: "n"(N) : "memory");
}
// K-permutation within each 32-float chunk: logical kk*8+j ->
//   j<4 : kk*8 + 2j          (pairs (k, k+4) become adjacent)
//   j>=4: kk*8 + 2(j-4) + 1
__device__ __forceinline__ int perm32(int l32) {
    const int j = l32 & 7;
    return (l32 & 24) + ((j < 4) ? (j << 1) : (((j - 4) << 1) + 1));
}
__device__ __forceinline__ float gelu_tanh(float a) {
    return 0.5f * a * (1.0f + tanhf(0.7978845608028654f * (a + 0.044715f * a * a * a)));
}

// m16n8k8 tf32 MMA (fp32 acc), baseline sm_80 PTX — valid on compute_103.
__device__ __forceinline__ void mma_tf32(float* c, const uint32_t* a, const uint32_t* b) {
    asm volatile(
        "mma.sync.aligned.m16n8k8.row.col.f32.tf32.tf32.f32 "
        "{%0,%1,%2,%3}, {%4,%5,%6,%7}, {%8,%9}, {%0,%1,%2,%3};"
        : "+f"(c[0]), "+f"(c[1]), "+f"(c[2]), "+f"(c[3])
        : "r"(a[0]), "r"(a[1]), "r"(a[2]), "r"(a[3]), "r"(b[0]), "r"(b[1]));
}

// ===================== LayerNorm -> g_Y (tf32, K-permuted) =====================
__global__ void __launch_bounds__(256) ln_kernel(const float* __restrict__ x,
                                                 const float* __restrict__ scale,
                                                 const float* __restrict__ bias) {
    __shared__ float red1[8], red2[8];
    const int row = blockIdx.x;
    const int tid = threadIdx.x, wid = tid >> 5, lid = tid & 31;
    const float* xr = x + (size_t)row * HID;

    float v[8];
#pragma unroll
    for (int i = 0; i < 8; i++) v[i] = xr[tid + i * 256];

    float s1 = 0.f, s2 = 0.f;
#pragma unroll
    for (int i = 0; i < 8; i++) { s1 += v[i]; s2 += v[i] * v[i]; }
#pragma unroll
    for (int o = 16; o > 0; o >>= 1) {
        s1 += __shfl_xor_sync(0xFFFFFFFF, s1, o);
        s2 += __shfl_xor_sync(0xFFFFFFFF, s2, o);
    }
    if (lid == 0) { red1[wid] = s1; red2[wid] = s2; }
    __syncthreads();
    if (tid == 0) {
        float t1 = 0.f, t2 = 0.f;
#pragma unroll
        for (int i = 0; i < 8; i++) { t1 += red1[i]; t2 += red2[i]; }
        red1[0] = t1; red2[0] = t2;
    }
    __syncthreads();
    const float mu  = red1[0] * (1.0f / HID);
    const float var = red2[0] * (1.0f / HID) - mu * mu;
    const float inv = rsqrtf(var + 1e-6f);

    float* yr = g_Y + (size_t)row * HID;
#pragma unroll
    for (int i = 0; i < 8; i++) {
        const int c = tid + i * 256;
        const int pc = (c & ~31) + perm32(c & 31);
        yr[pc] = rna_tf32((v[i] - mu) * inv * scale[c] + bias[c]);
    }
}

// ===================== transpose + tf32 round + K-perm =====================
// in: [R][C] row-major -> out: [C][R] row-major, out K-dim (=R) permuted per 32
__global__ void __launch_bounds__(256) transpose_kernel(const float* __restrict__ in,
                                                        float* __restrict__ out,
                                                        int R, int C) {
    __shared__ float t[32][33];
    const int bx = blockIdx.x, by = blockIdx.y;
    const int tx = threadIdx.x, ty = threadIdx.y;   // (32, 8)
    const int x = bx * 32 + tx;
#pragma unroll
    for (int j = 0; j < 32; j += 8)
        t[ty + j][tx] = in[(size_t)(by * 32 + ty + j) * C + x];
    __syncthreads();
    const int oxp = by * 32 + perm32(tx);
#pragma unroll
    for (int j = 0; j < 32; j += 8)
        out[(size_t)(bx * 32 + ty + j) * R + oxp] = rna_tf32(t[tx][ty + j]);
}

// ===================== tiled tf32 mma.sync GEMM =====================
// 256 threads, BM=128, BN=256, BK=32, 8 warps (2m x 4n), warp tile 64x64.
// Staging buffers are K-permuted -> all fragment loads are conflict-free LDS.64.
// MODE 0: acc over g_Y * [W1t gelu-rows | W1t linear-rows]; fused GeGLU -> g_Z (128 cols)
// MODE 1: g_Z * W2t -> d_out (256 cols)
#define BM 128
#define BN 256
#define BK 32
#define PADK 40                        // floats per smem row (8 pad; conflict-free LDS.64)
#define ROW_BYTES (PADK * 4)           // 160
#define STAGE_ROWS (BM + BN)           // 384
#define STAGE_BYTES (STAGE_ROWS * ROW_BYTES)   // 61440
#define STAGE_F2 (STAGE_ROWS * (PADK / 2))     // float2 per stage
#define STAGES 3
#define SMEM_NEED (STAGES * STAGE_BYTES)       // 184320

template <int MODE>
__global__ void __launch_bounds__(256, 1) gemm_kernel(float* __restrict__ outp) {
    constexpr int K  = (MODE == 0) ? HID : IDIM;
    constexpr int NC = K / BK;
    constexpr int numBn = (MODE == 0) ? (IDIM / 128) : (HID / BN);

    extern __shared__ float smem[];
    const uint32_t smaddr = smem_u32(smem);

    const int tid = threadIdx.x, wid = tid >> 5, lid = tid & 31;
    const int warp_m = wid & 1;        // 0..1 -> 64-row strip
    const int warp_n = wid >> 1;       // 0..3
    const int g  = lid >> 2;           // 0..7
    const int tg = lid & 3;            // 0..3

    // supertile remap: groups of 8 m-tiles sweep bn together (L2 reuse)
    const int bid   = blockIdx.x;
    const int group = bid / (8 * numBn);
    const int rem   = bid % (8 * numBn);
    const int m0    = (group * 8 + (rem & 7)) * BM;
    const int bn    = rem / 8;

    int nB0, nB1;
    if (MODE == 0) { nB0 = bn * 128; nB1 = IDIM + bn * 128; }
    else           { nB0 = bn * BN;  nB1 = nB0 + 128; }

    const float* __restrict__ A  = (MODE == 0) ? g_Y : g_Z;
    const float* __restrict__ Bw = (MODE == 0) ? g_W1t : g_W2t;

    const float* Ag  = A  + (size_t)m0  * K;
    const float* B0g = Bw + (size_t)nB0 * K;
    const float* B1g = Bw + (size_t)nB1 * K;

    // ---- producer: 12 x 16B chunks per thread per stage (rows: A 0-127, B0 128-255, B1 256-383)
    auto issue_stage = [&](int cc) {
        const uint32_t sd = smaddr + (uint32_t)(cc % STAGES) * STAGE_BYTES;
        const int kof = cc * BK;
#pragma unroll
        for (int j = 0; j < 12; ++j) {
            const int ci = tid + j * 256;
            const int r = ci >> 3, ch = ci & 7;
            const float* src;
            if      (r < 128) src = Ag  + (size_t)r * K         + kof + ch * 4;
            else if (r < 256) src = B0g + (size_t)(r - 128) * K + kof + ch * 4;
            else              src = B1g + (size_t)(r - 256) * K + kof + ch * 4;
            cp_async16(sd + r * ROW_BYTES + ch * 16, src);
        }
        cp_commit();
    };

    float acc[4][8][4];
#pragma unroll
    for (int mt = 0; mt < 4; ++mt)
#pragma unroll
        for (int nt = 0; nt < 8; ++nt)
#pragma unroll
            for (int q = 0; q < 4; ++q) acc[mt][nt][q] = 0.f;

    issue_stage(0);
    issue_stage(1);

    for (int c = 0; c < NC; ++c) {
        cp_wait<1>();
        __syncthreads();
        if (c + 2 < NC) issue_stage(c + 2); else cp_commit();

        const float2* sd2 = (const float2*)smem + (size_t)(c % STAGES) * STAGE_F2;

#pragma unroll
        for (int kk = 0; kk < 4; ++kk) {
            const int ko = kk * 4 + tg;   // float2 offset within row
            // A fragments: rows warp_m*64 + mt*16 + g (+8); .x = k0, .y = k0+4
            float2 af[4][2];
#pragma unroll
            for (int mt = 0; mt < 4; ++mt) {
                const float2* ap = sd2 + (size_t)(warp_m * 64 + mt * 16 + g) * (PADK / 2);
                af[mt][0] = ap[ko];
                af[mt][1] = ap[8 * (PADK / 2) + ko];
            }
            // B fragments: smem row 128 + (branch) + strip + nt*8 + g
            float2 bf[8];
#pragma unroll
            for (int nt = 0; nt < 8; ++nt) {
                int brow;
                if (MODE == 0) brow = 128 + ((nt >> 2) * 128) + warp_n * 32 + (nt & 3) * 8 + g;
                else           brow = 128 + warp_n * 64 + nt * 8 + g;
                bf[nt] = sd2[(size_t)brow * (PADK / 2) + ko];
            }
#pragma unroll
            for (int mt = 0; mt < 4; ++mt) {
                uint32_t a[4] = { __float_as_uint(af[mt][0].x), __float_as_uint(af[mt][1].x),
                                  __float_as_uint(af[mt][0].y), __float_as_uint(af[mt][1].y) };
#pragma unroll
                for (int nt = 0; nt < 8; ++nt) {
                    uint32_t b[2] = { __float_as_uint(bf[nt].x), __float_as_uint(bf[nt].y) };
                    mma_tf32(acc[mt][nt], a, b);
                }
            }
        }
    }

    // ---- epilogue ----
    if (MODE == 0) {
        // z = gelu(left) * right; store K-permuted into g_Z.
        // C frag cols 2tg,2tg+1 -> permuted positions pp, pp+2
        const int pp = (tg & 1) * 4 + (tg >> 1);
#pragma unroll
        for (int mt = 0; mt < 4; ++mt) {
            const int r0 = m0 + warp_m * 64 + mt * 16 + g;
#pragma unroll
            for (int nt = 0; nt < 4; ++nt) {
                const int colb = bn * 128 + warp_n * 32 + nt * 8;
                const float* L = acc[mt][nt];
                const float* R = acc[mt][nt + 4];
                float* z0 = g_Z + (size_t)r0 * IDIM + colb;
                float* z1 = g_Z + (size_t)(r0 + 8) * IDIM + colb;
                z0[pp]     = rna_tf32(gelu_tanh(L[0]) * R[0]);
                z0[pp + 2] = rna_tf32(gelu_tanh(L[1]) * R[1]);
                z1[pp]     = rna_tf32(gelu_tanh(L[2]) * R[2]);
                z1[pp + 2] = rna_tf32(gelu_tanh(L[3]) * R[3]);
            }
        }
    } else {
#pragma unroll
        for (int mt = 0; mt < 4; ++mt) {
            const int r0 = m0 + warp_m * 64 + mt * 16 + g;
#pragma unroll
            for (int nt = 0; nt < 8; ++nt) {
                const int col = nB0 + warp_n * 64 + nt * 8 + tg * 2;
                *(float2*)(outp + (size_t)r0 * HID + col) =
                    make_float2(acc[mt][nt][0], acc[mt][nt][1]);
                *(float2*)(outp + (size_t)(r0 + 8) * HID + col) =
                    make_float2(acc[mt][nt][2], acc[mt][nt][3]);
            }
        }
    }
}

// ===================== launch =====================
extern "C" void kernel_launch(void* const* d_in, const int* in_sizes, int n_in,
                              void* d_out, int out_size) {
    const float* x     = (const float*)d_in[0];
    const float* scale = (const float*)d_in[1];
    const float* bias  = (const float*)d_in[2];
    const float* k1    = (const float*)d_in[3];   // [2048][16384]
    const float* k2    = (const float*)d_in[4];   // [8192][2048]
    float* out = (float*)d_out;

    float* w1t; cudaGetSymbolAddress((void**)&w1t, g_W1t);
    float* w2t; cudaGetSymbolAddress((void**)&w2t, g_W2t);

    cudaFuncSetAttribute(gemm_kernel<0>, cudaFuncAttributeMaxDynamicSharedMemorySize, SMEM_NEED);
    cudaFuncSetAttribute(gemm_kernel<1>, cudaFuncAttributeMaxDynamicSharedMemorySize, SMEM_NEED);

    // 1) LayerNorm -> g_Y (K-permuted tf32)
    ln_kernel<<<TOKENS, 256>>>(x, scale, bias);

    // 2) W1 [2048][16384] -> g_W1t [16384][2048] (K-permuted tf32)
    transpose_kernel<<<dim3(2 * IDIM / 32, HID / 32), dim3(32, 8)>>>(k1, w1t, HID, 2 * IDIM);

    // 3) W2 [8192][2048] -> g_W2t [2048][8192] (K-permuted tf32)
    transpose_kernel<<<dim3(HID / 32, IDIM / 32), dim3(32, 8)>>>(k2, w2t, IDIM, HID);

    // 4) GEMM1 + fused GeGLU -> g_Z   (64 m-tiles x 64 z-col-tiles)
    gemm_kernel<0><<<64 * 64, 256, SMEM_NEED>>>(out);

    // 5) GEMM2 -> out                 (64 m-tiles x 8 n-tiles)
    gemm_kernel<1><<<64 * 8, 256, SMEM_NEED>>>(out);
}

// round 6
// speedup vs baseline: 1.3490x; 1.3490x over previous
#include <cuda_runtime.h>
#include <cstdint>

// ===================== problem sizes =====================
#define TOKENS 8192      // B*S = 4*2048
#define HID    2048
#define IDIM   8192

// ===================== scratch (device globals) =====================
__device__ float g_Y  [TOKENS * HID];          // 64 MB  LN output (tf32, K-permuted)
__device__ float g_W1t[2 * IDIM * HID];        // 128 MB W1^T [16384][2048] (tf32, K-perm)
__device__ float g_W2t[HID * IDIM];            // 64 MB  W2^T [2048][8192]  (tf32, K-perm)
__device__ float g_Z  [TOKENS * IDIM];         // 256 MB GeGLU output (tf32, K-perm)

// ===================== helpers =====================
__device__ __forceinline__ uint32_t smem_u32(const void* p) {
    uint32_t a;
    asm("{ .reg .u64 t; cvta.to.shared.u64 t, %1; cvt.u32.u64 %0, t; }" : "=r"(a) : "l"(p));
    return a;
}
__device__ __forceinline__ float rna_tf32(float f) {
    uint32_t u;
    asm("cvt.rna.tf32.f32 %0, %1;" : "=r"(u) : "f"(f));
    return __uint_as_float(u);
}
__device__ __forceinline__ void cp_async16(uint32_t dst, const void* src) {
    asm volatile("cp.async.cg.shared.global [%0], [%1], 16;" :: "r"(dst), "l"(src) : "memory");
}
__device__ __forceinline__ void cp_commit() {
    asm volatile("cp.async.commit_group;" ::: "memory");
}
template <int N>
__device__ __forceinline__ void cp_wait() {
    asm volatile("cp.async.wait_group %0;" :: "n"(N) : "memory");
}
// K-permutation within each 32-float chunk: logical kk*8+j ->
//   j<4 : kk*8 + 2j ; j>=4: kk*8 + 2(j-4)+1   (pairs (k, k+4) adjacent)
__device__ __forceinline__ int perm32(int l32) {
    const int j = l32 & 7;
    return (l32 & 24) + ((j < 4) ? (j << 1) : (((j - 4) << 1) + 1));
}
__device__ __forceinline__ float gelu_tanh(float a) {
    return 0.5f * a * (1.0f + tanhf(0.7978845608028654f * (a + 0.044715f * a * a * a)));
}

// m16n8k8 tf32 MMA (fp32 acc), baseline sm_80 PTX — valid on compute_103.
__device__ __forceinline__ void mma_tf32(float* c, const uint32_t* a, const uint32_t* b) {
    asm volatile(
        "mma.sync.aligned.m16n8k8.row.col.f32.tf32.tf32.f32 "
        "{%0,%1,%2,%3}, {%4,%5,%6,%7}, {%8,%9}, {%0,%1,%2,%3};"
        : "+f"(c[0]), "+f"(c[1]), "+f"(c[2]), "+f"(c[3])
        : "r"(a[0]), "r"(a[1]), "r"(a[2]), "r"(a[3]), "r"(b[0]), "r"(b[1]));
}

// ===================== LayerNorm -> g_Y (tf32, K-permuted) =====================
__global__ void __launch_bounds__(256) ln_kernel(const float* __restrict__ x,
                                                 const float* __restrict__ scale,
                                                 const float* __restrict__ bias) {
    __shared__ float red1[8], red2[8];
    const int row = blockIdx.x;
    const int tid = threadIdx.x, wid = tid >> 5, lid = tid & 31;
    const float* xr = x + (size_t)row * HID;

    float v[8];
#pragma unroll
    for (int i = 0; i < 8; i++) v[i] = xr[tid + i * 256];

    float s1 = 0.f, s2 = 0.f;
#pragma unroll
    for (int i = 0; i < 8; i++) { s1 += v[i]; s2 += v[i] * v[i]; }
#pragma unroll
    for (int o = 16; o > 0; o >>= 1) {
        s1 += __shfl_xor_sync(0xFFFFFFFF, s1, o);
        s2 += __shfl_xor_sync(0xFFFFFFFF, s2, o);
    }
    if (lid == 0) { red1[wid] = s1; red2[wid] = s2; }
    __syncthreads();
    if (tid == 0) {
        float t1 = 0.f, t2 = 0.f;
#pragma unroll
        for (int i = 0; i < 8; i++) { t1 += red1[i]; t2 += red2[i]; }
        red1[0] = t1; red2[0] = t2;
    }
    __syncthreads();
    const float mu  = red1[0] * (1.0f / HID);
    const float var = red2[0] * (1.0f / HID) - mu * mu;
    const float inv = rsqrtf(var + 1e-6f);

    float* yr = g_Y + (size_t)row * HID;
#pragma unroll
    for (int i = 0; i < 8; i++) {
        const int c = tid + i * 256;
        const int pc = (c & ~31) + perm32(c & 31);
        yr[pc] = rna_tf32((v[i] - mu) * inv * scale[c] + bias[c]);
    }
}

// ===================== transpose + tf32 round + K-perm =====================
// in: [R][C] row-major -> out: [C][R] row-major, out K-dim (=R) permuted per 32
__global__ void __launch_bounds__(256) transpose_kernel(const float* __restrict__ in,
                                                        float* __restrict__ out,
                                                        int R, int C) {
    __shared__ float t[32][33];
    const int bx = blockIdx.x, by = blockIdx.y;
    const int tx = threadIdx.x, ty = threadIdx.y;   // (32, 8)
    const int x = bx * 32 + tx;
#pragma unroll
    for (int j = 0; j < 32; j += 8)
        t[ty + j][tx] = in[(size_t)(by * 32 + ty + j) * C + x];
    __syncthreads();
    const int oxp = by * 32 + perm32(tx);
#pragma unroll
    for (int j = 0; j < 32; j += 8)
        out[(size_t)(bx * 32 + ty + j) * R + oxp] = rna_tf32(t[tx][ty + j]);
}

// ===================== tiled tf32 mma.sync GEMM =====================
// 512 threads, BM=128, BN=256, BK=32, 16 warps (4m x 4n), warp tile 32x64.
// K-permuted staging -> conflict-free LDS.64 fragment loads (PADK=40 verified).
// MODE 0: acc = g_Y * [W1t gelu-rows | W1t linear-rows]; fused GeGLU -> g_Z (128 cols)
// MODE 1: g_Z * W2t -> d_out (256 cols)
#define BM 128
#define BN 256
#define BK 32
#define PADK 40
#define ROW_BYTES (PADK * 4)                   // 160
#define STAGE_ROWS (BM + BN)                   // 384
#define STAGE_BYTES (STAGE_ROWS * ROW_BYTES)   // 61440
#define STAGE_F2 (STAGE_ROWS * (PADK / 2))
#define STAGES 3
#define SMEM_NEED (STAGES * STAGE_BYTES)       // 184320

template <int MODE>
__global__ void __launch_bounds__(512, 1) gemm_kernel(float* __restrict__ outp) {
    constexpr int K  = (MODE == 0) ? HID : IDIM;
    constexpr int NC = K / BK;
    constexpr int numBn = (MODE == 0) ? (IDIM / 128) : (HID / BN);

    extern __shared__ float smem[];
    const uint32_t smaddr = smem_u32(smem);

    const int tid = threadIdx.x, wid = tid >> 5, lid = tid & 31;
    const int warp_m = wid & 3;        // 0..3 -> 32-row strip
    const int warp_n = wid >> 2;       // 0..3 -> 64-col strip (32 per branch in MODE 0)
    const int g  = lid >> 2;           // 0..7
    const int tg = lid & 3;            // 0..3

    // supertile remap: groups of 8 m-tiles sweep bn together (L2 reuse)
    const int bid   = blockIdx.x;
    const int group = bid / (8 * numBn);
    const int rem   = bid % (8 * numBn);
    const int m0    = (group * 8 + (rem & 7)) * BM;
    const int bn    = rem / 8;

    int nB0, nB1;
    if (MODE == 0) { nB0 = bn * 128; nB1 = IDIM + bn * 128; }
    else           { nB0 = bn * BN;  nB1 = nB0 + 128; }

    const float* __restrict__ A  = (MODE == 0) ? g_Y : g_Z;
    const float* __restrict__ Bw = (MODE == 0) ? g_W1t : g_W2t;

    const float* Ag  = A  + (size_t)m0  * K;
    const float* B0g = Bw + (size_t)nB0 * K;
    const float* B1g = Bw + (size_t)nB1 * K;

    // producer chunk assignments (uniform branch per pair; 6 x 16B per thread)
    const int rA0 = tid >> 3,           chA0 = tid & 7;           // rows   0..63
    const int rA1 = (tid + 512) >> 3,   chA1 = tid & 7;           // rows  64..127
    const int rB0a = tid >> 3,          rB0b = (tid + 512) >> 3;  // B0 local rows
    const int rB1a = tid >> 3,          rB1b = (tid + 512) >> 3;  // B1 local rows

    auto issue_stage = [&](int cc) {
        const uint32_t sd = smaddr + (uint32_t)(cc % STAGES) * STAGE_BYTES;
        const int kof = cc * BK;
        const int chB = tid & 7;
        cp_async16(sd + rA0 * ROW_BYTES + chA0 * 16,           Ag  + (size_t)rA0  * K + kof + chA0 * 4);
        cp_async16(sd + rA1 * ROW_BYTES + chA1 * 16,           Ag  + (size_t)rA1  * K + kof + chA1 * 4);
        cp_async16(sd + (128 + rB0a) * ROW_BYTES + chB * 16,   B0g + (size_t)rB0a * K + kof + chB * 4);
        cp_async16(sd + (128 + rB0b) * ROW_BYTES + chB * 16,   B0g + (size_t)rB0b * K + kof + chB * 4);
        cp_async16(sd + (256 + rB1a) * ROW_BYTES + chB * 16,   B1g + (size_t)rB1a * K + kof + chB * 4);
        cp_async16(sd + (256 + rB1b) * ROW_BYTES + chB * 16,   B1g + (size_t)rB1b * K + kof + chB * 4);
        cp_commit();
    };

    float acc[2][8][4];
#pragma unroll
    for (int mt = 0; mt < 2; ++mt)
#pragma unroll
        for (int nt = 0; nt < 8; ++nt)
#pragma unroll
            for (int q = 0; q < 4; ++q) acc[mt][nt][q] = 0.f;

    issue_stage(0);
    issue_stage(1);

    for (int c = 0; c < NC; ++c) {
        cp_wait<1>();
        __syncthreads();
        if (c + 2 < NC) issue_stage(c + 2); else cp_commit();

        const float2* sd2 = (const float2*)smem + (size_t)(c % STAGES) * STAGE_F2;

#pragma unroll
        for (int kk = 0; kk < 4; ++kk) {
            const int ko = kk * 4 + tg;   // float2 index in row; holds (k0, k0+4)
            float2 af[2][2];
#pragma unroll
            for (int mt = 0; mt < 2; ++mt) {
                const float2* ap = sd2 + (size_t)(warp_m * 32 + mt * 16 + g) * (PADK / 2);
                af[mt][0] = ap[ko];
                af[mt][1] = ap[8 * (PADK / 2) + ko];
            }
            float2 bf[8];
#pragma unroll
            for (int nt = 0; nt < 8; ++nt) {
                int brow;
                if (MODE == 0) brow = 128 + ((nt >> 2) * 128) + warp_n * 32 + (nt & 3) * 8 + g;
                else           brow = 128 + warp_n * 64 + nt * 8 + g;
                bf[nt] = sd2[(size_t)brow * (PADK / 2) + ko];
            }
#pragma unroll
            for (int mt = 0; mt < 2; ++mt) {
                uint32_t a[4] = { __float_as_uint(af[mt][0].x), __float_as_uint(af[mt][1].x),
                                  __float_as_uint(af[mt][0].y), __float_as_uint(af[mt][1].y) };
#pragma unroll
                for (int nt = 0; nt < 8; ++nt) {
                    uint32_t b[2] = { __float_as_uint(bf[nt].x), __float_as_uint(bf[nt].y) };
                    mma_tf32(acc[mt][nt], a, b);
                }
            }
        }
    }

    // ---- epilogue ----
    if (MODE == 0) {
        // z = gelu(left) * right; stored K-permuted into g_Z.
        // logical frag cols (2tg, 2tg+1) -> permuted positions (pp, pp+2)
        const int pp = (tg & 1) * 4 + (tg >> 1);
#pragma unroll
        for (int mt = 0; mt < 2; ++mt) {
            const int r0 = m0 + warp_m * 32 + mt * 16 + g;
#pragma unroll
            for (int nt = 0; nt < 4; ++nt) {
                const int colb = bn * 128 + warp_n * 32 + nt * 8;
                const float* L = acc[mt][nt];
                const float* R = acc[mt][nt + 4];
                float* z0 = g_Z + (size_t)r0 * IDIM + colb;
                float* z1 = g_Z + (size_t)(r0 + 8) * IDIM + colb;
                z0[pp]     = rna_tf32(gelu_tanh(L[0]) * R[0]);
                z0[pp + 2] = rna_tf32(gelu_tanh(L[1]) * R[1]);
                z1[pp]     = rna_tf32(gelu_tanh(L[2]) * R[2]);
                z1[pp + 2] = rna_tf32(gelu_tanh(L[3]) * R[3]);
            }
        }
    } else {
#pragma unroll
        for (int mt = 0; mt < 2; ++mt) {
            const int r0 = m0 + warp_m * 32 + mt * 16 + g;
#pragma unroll
            for (int nt = 0; nt < 8; ++nt) {
                const int col = nB0 + warp_n * 64 + nt * 8 + tg * 2;
                *(float2*)(outp + (size_t)r0 * HID + col) =
                    make_float2(acc[mt][nt][0], acc[mt][nt][1]);
                *(float2*)(outp + (size_t)(r0 + 8) * HID + col) =
                    make_float2(acc[mt][nt][2], acc[mt][nt][3]);
            }
        }
    }
}

// ===================== launch =====================
extern "C" void kernel_launch(void* const* d_in, const int* in_sizes, int n_in,
                              void* d_out, int out_size) {
    const float* x     = (const float*)d_in[0];
    const float* scale = (const float*)d_in[1];
    const float* bias  = (const float*)d_in[2];
    const float* k1    = (const float*)d_in[3];   // [2048][16384]
    const float* k2    = (const float*)d_in[4];   // [8192][2048]
    float* out = (float*)d_out;

    float* w1t; cudaGetSymbolAddress((void**)&w1t, g_W1t);
    float* w2t; cudaGetSymbolAddress((void**)&w2t, g_W2t);

    cudaFuncSetAttribute(gemm_kernel<0>, cudaFuncAttributeMaxDynamicSharedMemorySize, SMEM_NEED);
    cudaFuncSetAttribute(gemm_kernel<1>, cudaFuncAttributeMaxDynamicSharedMemorySize, SMEM_NEED);

    // 1) LayerNorm -> g_Y (K-permuted tf32)
    ln_kernel<<<TOKENS, 256>>>(x, scale, bias);

    // 2) W1 [2048][16384] -> g_W1t [16384][2048] (K-permuted tf32)
    transpose_kernel<<<dim3(2 * IDIM / 32, HID / 32), dim3(32, 8)>>>(k1, w1t, HID, 2 * IDIM);

    // 3) W2 [8192][2048] -> g_W2t [2048][8192] (K-permuted tf32)
    transpose_kernel<<<dim3(HID / 32, IDIM / 32), dim3(32, 8)>>>(k2, w2t, IDIM, HID);

    // 4) GEMM1 + fused GeGLU -> g_Z   (64 m-tiles x 64 z-col-tiles)
    gemm_kernel<0><<<64 * 64, 512, SMEM_NEED>>>(out);

    // 5) GEMM2 -> out                 (64 m-tiles x 8 n-tiles)
    gemm_kernel<1><<<64 * 8, 512, SMEM_NEED>>>(out);
}

// round 7
// speedup vs baseline: 1.4706x; 1.0901x over previous
#include <cuda_runtime.h>
#include <cstdint>

// ===================== problem sizes =====================
#define TOKENS 8192      // B*S = 4*2048
#define HID    2048
#define IDIM   8192

// ===================== scratch (device globals) =====================
__device__ float g_Y  [TOKENS * HID];          // 64 MB  LN output (tf32, K-permuted)
__device__ float g_W1t[2 * IDIM * HID];        // 128 MB W1^T [16384][2048] (tf32, K-perm)
__device__ float g_W2t[HID * IDIM];            // 64 MB  W2^T [2048][8192]  (tf32, K-perm)
__device__ float g_Z  [TOKENS * IDIM];         // 256 MB GeGLU output (tf32, K-perm)

// ===================== helpers =====================
__device__ __forceinline__ uint32_t smem_u32(const void* p) {
    uint32_t a;
    asm("{ .reg .u64 t; cvta.to.shared.u64 t, %1; cvt.u32.u64 %0, t; }" : "=r"(a) : "l"(p));
    return a;
}
__device__ __forceinline__ float rna_tf32(float f) {
    uint32_t u;
    asm("cvt.rna.tf32.f32 %0, %1;" : "=r"(u) : "f"(f));
    return __uint_as_float(u);
}
__device__ __forceinline__ void cp_async16(uint32_t dst, const void* src) {
    asm volatile("cp.async.cg.shared.global [%0], [%1], 16;" :: "r"(dst), "l"(src) : "memory");
}
__device__ __forceinline__ void cp_commit() {
    asm volatile("cp.async.commit_group;" ::: "memory");
}
template <int N>
__device__ __forceinline__ void cp_wait() {
    asm volatile("cp.async.wait_group %0;" :: "n"(N) : "memory");
}
// K-permutation within each 32-float chunk: logical kk*8+j ->
//   j<4 : kk*8 + 2j ; j>=4: kk*8 + 2(j-4)+1   (pairs (k, k+4) adjacent)
__device__ __forceinline__ int perm32(int l32) {
    const int j = l32 & 7;
    return (l32 & 24) + ((j < 4) ? (j << 1) : (((j - 4) << 1) + 1));
}
__device__ __forceinline__ float gelu_tanh(float a) {
    return 0.5f * a * (1.0f + tanhf(0.7978845608028654f * (a + 0.044715f * a * a * a)));
}

// m16n8k8 tf32 MMA (fp32 acc); operands consumed directly, no repacking.
__device__ __forceinline__ void mma_tf32(float* c, uint2 a0, uint2 a1, uint2 b) {
    asm volatile(
        "mma.sync.aligned.m16n8k8.row.col.f32.tf32.tf32.f32 "
        "{%0,%1,%2,%3}, {%4,%5,%6,%7}, {%8,%9}, {%0,%1,%2,%3};"
        : "+f"(c[0]), "+f"(c[1]), "+f"(c[2]), "+f"(c[3])
        : "r"(a0.x), "r"(a1.x), "r"(a0.y), "r"(a1.y), "r"(b.x), "r"(b.y));
}

// ===================== LayerNorm -> g_Y (tf32, K-permuted) =====================
__global__ void __launch_bounds__(256) ln_kernel(const float* __restrict__ x,
                                                 const float* __restrict__ scale,
                                                 const float* __restrict__ bias) {
    __shared__ float red1[8], red2[8];
    const int row = blockIdx.x;
    const int tid = threadIdx.x, wid = tid >> 5, lid = tid & 31;
    const float* xr = x + (size_t)row * HID;

    float v[8];
#pragma unroll
    for (int i = 0; i < 8; i++) v[i] = xr[tid + i * 256];

    float s1 = 0.f, s2 = 0.f;
#pragma unroll
    for (int i = 0; i < 8; i++) { s1 += v[i]; s2 += v[i] * v[i]; }
#pragma unroll
    for (int o = 16; o > 0; o >>= 1) {
        s1 += __shfl_xor_sync(0xFFFFFFFF, s1, o);
        s2 += __shfl_xor_sync(0xFFFFFFFF, s2, o);
    }
    if (lid == 0) { red1[wid] = s1; red2[wid] = s2; }
    __syncthreads();
    if (tid == 0) {
        float t1 = 0.f, t2 = 0.f;
#pragma unroll
        for (int i = 0; i < 8; i++) { t1 += red1[i]; t2 += red2[i]; }
        red1[0] = t1; red2[0] = t2;
    }
    __syncthreads();
    const float mu  = red1[0] * (1.0f / HID);
    const float var = red2[0] * (1.0f / HID) - mu * mu;
    const float inv = rsqrtf(var + 1e-6f);

    float* yr = g_Y + (size_t)row * HID;
#pragma unroll
    for (int i = 0; i < 8; i++) {
        const int c = tid + i * 256;
        const int pc = (c & ~31) + perm32(c & 31);
        yr[pc] = rna_tf32((v[i] - mu) * inv * scale[c] + bias[c]);
    }
}

// ===================== transpose + tf32 round + K-perm =====================
__global__ void __launch_bounds__(256) transpose_kernel(const float* __restrict__ in,
                                                        float* __restrict__ out,
                                                        int R, int C) {
    __shared__ float t[32][33];
    const int bx = blockIdx.x, by = blockIdx.y;
    const int tx = threadIdx.x, ty = threadIdx.y;   // (32, 8)
    const int x = bx * 32 + tx;
#pragma unroll
    for (int j = 0; j < 32; j += 8)
        t[ty + j][tx] = in[(size_t)(by * 32 + ty + j) * C + x];
    __syncthreads();
    const int oxp = by * 32 + perm32(tx);
#pragma unroll
    for (int j = 0; j < 32; j += 8)
        out[(size_t)(bx * 32 + ty + j) * R + oxp] = rna_tf32(t[tx][ty + j]);
}

// ===================== tiled tf32 mma.sync GEMM =====================
// 256 threads, BM=128, BN=128, BK=32, 8 warps (4m x 2n), warp tile 32x64.
// 2 stages x 40 KB -> 2 CTAs/SM (cross-CTA barrier overlap).
// MODE 0: B = [64 gelu rows | 64 linear rows]; fused GeGLU -> g_Z (64 cols/blk)
// MODE 1: g_Z * W2t -> d_out (128 cols/blk)
#define BM 128
#define BN 128
#define BK 32
#define PADK 40
#define ROW_BYTES (PADK * 4)                   // 160
#define STAGE_ROWS (BM + BN)                   // 256
#define STAGE_BYTES (STAGE_ROWS * ROW_BYTES)   // 40960
#define STAGE_U2 (STAGE_ROWS * (PADK / 2))     // uint2 per stage
#define STAGES 2
#define SMEM_NEED (STAGES * STAGE_BYTES)       // 81920

template <int MODE>
__global__ void __launch_bounds__(256, 2) gemm_kernel(float* __restrict__ outp) {
    constexpr int K  = (MODE == 0) ? HID : IDIM;
    constexpr int NC = K / BK;
    constexpr int numBn = (MODE == 0) ? (IDIM / 64) : (HID / BN);   // 128 / 16

    extern __shared__ float smem[];
    const uint32_t smaddr = smem_u32(smem);

    const int tid = threadIdx.x, wid = tid >> 5, lid = tid & 31;
    const int warp_m = wid & 3;        // 0..3 -> 32-row strip
    const int warp_n = wid >> 2;       // 0..1 -> 64-col strip
    const int g  = lid >> 2;           // 0..7
    const int tg = lid & 3;            // 0..3

    // supertile remap: groups of 8 m-tiles sweep bn together (L2 reuse)
    const int bid   = blockIdx.x;
    const int group = bid / (8 * numBn);
    const int rem   = bid % (8 * numBn);
    const int m0    = (group * 8 + (rem & 7)) * BM;
    const int bn    = rem / 8;

    int nB0, nB1;
    if (MODE == 0) { nB0 = bn * 64;  nB1 = IDIM + bn * 64; }   // 64+64 rows
    else           { nB0 = bn * BN;  nB1 = nB0 + 64; }         // 128 contiguous

    const float* __restrict__ A  = (MODE == 0) ? g_Y : g_Z;
    const float* __restrict__ Bw = (MODE == 0) ? g_W1t : g_W2t;

    const float* Ag  = A  + (size_t)m0  * K;
    const float* B0g = Bw + (size_t)nB0 * K;
    const float* B1g = Bw + (size_t)nB1 * K;

    // producer: 8 x 16B chunks per thread (rows: A 0-127, B0 128-191, B1 192-255)
    const int ch = tid & 7;
    const int pr = tid >> 3;           // 0..31
    auto issue_stage = [&](int cc) {
        const uint32_t sd = smaddr + (uint32_t)(cc & 1) * STAGE_BYTES;
        const int kof = cc * BK;
#pragma unroll
        for (int j = 0; j < 4; ++j) {  // A rows pr + 32j
            const int r = pr + j * 32;
            cp_async16(sd + r * ROW_BYTES + ch * 16, Ag + (size_t)r * K + kof + ch * 4);
        }
#pragma unroll
        for (int j = 0; j < 2; ++j) {  // B0 local rows pr + 32j
            const int r = pr + j * 32;
            cp_async16(sd + (128 + r) * ROW_BYTES + ch * 16, B0g + (size_t)r * K + kof + ch * 4);
        }
#pragma unroll
        for (int j = 0; j < 2; ++j) {  // B1 local rows pr + 32j
            const int r = pr + j * 32;
            cp_async16(sd + (192 + r) * ROW_BYTES + ch * 16, B1g + (size_t)r * K + kof + ch * 4);
        }
        cp_commit();
    };

    float acc[2][8][4];
#pragma unroll
    for (int mt = 0; mt < 2; ++mt)
#pragma unroll
        for (int nt = 0; nt < 8; ++nt)
#pragma unroll
            for (int q = 0; q < 4; ++q) acc[mt][nt][q] = 0.f;

    issue_stage(0);

    for (int c = 0; c < NC; ++c) {
        __syncthreads();
        if (c + 1 < NC) issue_stage(c + 1); else cp_commit();
        cp_wait<1>();
        __syncthreads();

        const uint2* sd2 = (const uint2*)smem + (size_t)(c & 1) * STAGE_U2;

#pragma unroll
        for (int kk = 0; kk < 4; ++kk) {
            const int ko = kk * 4 + tg;   // uint2 index in row; holds (k0, k0+4)
            uint2 au[2][2];
#pragma unroll
            for (int mt = 0; mt < 2; ++mt) {
                const uint2* ap = sd2 + (size_t)(warp_m * 32 + mt * 16 + g) * (PADK / 2);
                au[mt][0] = ap[ko];
                au[mt][1] = ap[8 * (PADK / 2) + ko];
            }
            uint2 bu[8];
#pragma unroll
            for (int nt = 0; nt < 8; ++nt) {
                int brow;
                if (MODE == 0) brow = 128 + ((nt >> 2) * 64) + warp_n * 32 + (nt & 3) * 8 + g;
                else           brow = 128 + warp_n * 64 + nt * 8 + g;
                bu[nt] = sd2[(size_t)brow * (PADK / 2) + ko];
            }
#pragma unroll
            for (int mt = 0; mt < 2; ++mt)
#pragma unroll
                for (int nt = 0; nt < 8; ++nt)
                    mma_tf32(acc[mt][nt], au[mt][0], au[mt][1], bu[nt]);
        }
    }

    // ---- epilogue ----
    if (MODE == 0) {
        // z = gelu(left) * right; stored K-permuted into g_Z (64 cols per block).
        // logical frag cols (2tg, 2tg+1) -> permuted positions (pp, pp+2)
        const int pp = (tg & 1) * 4 + (tg >> 1);
#pragma unroll
        for (int mt = 0; mt < 2; ++mt) {
            const int r0 = m0 + warp_m * 32 + mt * 16 + g;
#pragma unroll
            for (int nt = 0; nt < 4; ++nt) {
                const int colb = bn * 64 + warp_n * 32 + nt * 8;
                const float* L = acc[mt][nt];       // gelu branch
                const float* R = acc[mt][nt + 4];   // linear branch
                float* z0 = g_Z + (size_t)r0 * IDIM + colb;
                float* z1 = g_Z + (size_t)(r0 + 8) * IDIM + colb;
                z0[pp]     = rna_tf32(gelu_tanh(L[0]) * R[0]);
                z0[pp + 2] = rna_tf32(gelu_tanh(L[1]) * R[1]);
                z1[pp]     = rna_tf32(gelu_tanh(L[2]) * R[2]);
                z1[pp + 2] = rna_tf32(gelu_tanh(L[3]) * R[3]);
            }
        }
    } else {
#pragma unroll
        for (int mt = 0; mt < 2; ++mt) {
            const int r0 = m0 + warp_m * 32 + mt * 16 + g;
#pragma unroll
            for (int nt = 0; nt < 8; ++nt) {
                const int col = nB0 + warp_n * 64 + nt * 8 + tg * 2;
                *(float2*)(outp + (size_t)r0 * HID + col) =
                    make_float2(acc[mt][nt][0], acc[mt][nt][1]);
                *(float2*)(outp + (size_t)(r0 + 8) * HID + col) =
                    make_float2(acc[mt][nt][2], acc[mt][nt][3]);
            }
        }
    }
}

// ===================== launch =====================
extern "C" void kernel_launch(void* const* d_in, const int* in_sizes, int n_in,
                              void* d_out, int out_size) {
    const float* x     = (const float*)d_in[0];
    const float* scale = (const float*)d_in[1];
    const float* bias  = (const float*)d_in[2];
    const float* k1    = (const float*)d_in[3];   // [2048][16384]
    const float* k2    = (const float*)d_in[4];   // [8192][2048]
    float* out = (float*)d_out;

    float* w1t; cudaGetSymbolAddress((void**)&w1t, g_W1t);
    float* w2t; cudaGetSymbolAddress((void**)&w2t, g_W2t);

    cudaFuncSetAttribute(gemm_kernel<0>, cudaFuncAttributeMaxDynamicSharedMemorySize, SMEM_NEED);
    cudaFuncSetAttribute(gemm_kernel<1>, cudaFuncAttributeMaxDynamicSharedMemorySize, SMEM_NEED);

    // 1) LayerNorm -> g_Y (K-permuted tf32)
    ln_kernel<<<TOKENS, 256>>>(x, scale, bias);

    // 2) W1 [2048][16384] -> g_W1t [16384][2048] (K-permuted tf32)
    transpose_kernel<<<dim3(2 * IDIM / 32, HID / 32), dim3(32, 8)>>>(k1, w1t, HID, 2 * IDIM);

    // 3) W2 [8192][2048] -> g_W2t [2048][8192] (K-permuted tf32)
    transpose_kernel<<<dim3(HID / 32, IDIM / 32), dim3(32, 8)>>>(k2, w2t, IDIM, HID);

    // 4) GEMM1 + fused GeGLU -> g_Z   (64 m-tiles x 128 z-col-tiles)
    gemm_kernel<0><<<64 * 128, 256, SMEM_NEED>>>(out);

    // 5) GEMM2 -> out                 (64 m-tiles x 16 n-tiles)
    gemm_kernel<1><<<64 * 16, 256, SMEM_NEED>>>(out);
}

// round 9
// speedup vs baseline: 1.6346x; 1.1115x over previous
#include <cuda_runtime.h>
#include <cstdint>

// ===================== problem sizes =====================
#define TOKENS 8192      // B*S = 4*2048
#define HID    2048
#define IDIM   8192

// ===================== scratch (device globals) =====================
__device__ float g_Y  [TOKENS * HID];          // 64 MB  LN output (tf32, K-permuted)
__device__ float g_W1t[2 * IDIM * HID];        // 128 MB W1^T [16384][2048] (tf32, K-perm)
__device__ float g_W2t[HID * IDIM];            // 64 MB  W2^T [2048][8192]  (tf32, K-perm)
__device__ float g_Z  [TOKENS * IDIM];         // 256 MB GeGLU output (tf32, K-perm)

// ===================== helpers =====================
__device__ __forceinline__ uint32_t smem_u32(const void* p) {
    uint32_t a;
    asm("{ .reg .u64 t; cvta.to.shared.u64 t, %1; cvt.u32.u64 %0, t; }" : "=r"(a) : "l"(p));
    return a;
}
__device__ __forceinline__ float rna_tf32(float f) {
    uint32_t u;
    asm("cvt.rna.tf32.f32 %0, %1;" : "=r"(u) : "f"(f));
    return __uint_as_float(u);
}
__device__ __forceinline__ void cp_async16(uint32_t dst, const void* src) {
    asm volatile("cp.async.cg.shared.global [%0], [%1], 16;" :: "r"(dst), "l"(src) : "memory");
}
__device__ __forceinline__ void cp_commit() {
    asm volatile("cp.async.commit_group;" ::: "memory");
}
template <int N>
__device__ __forceinline__ void cp_wait() {
    asm volatile("cp.async.wait_group %0;" :: "n"(N) : "memory");
}
// K-permutation within each 32-float chunk: logical kk*8+j ->
//   j<4 : kk*8 + 2j ; j>=4: kk*8 + 2(j-4)+1   (pairs (k, k+4) adjacent)
__device__ __forceinline__ int perm32(int l32) {
    const int j = l32 & 7;
    return (l32 & 24) + ((j < 4) ? (j << 1) : (((j - 4) << 1) + 1));
}
__device__ __forceinline__ float gelu_tanh(float a) {
    return 0.5f * a * (1.0f + tanhf(0.7978845608028654f * (a + 0.044715f * a * a * a)));
}

// m16n8k8 tf32 MMA (fp32 acc); operands consumed directly, no repacking.
__device__ __forceinline__ void mma_tf32(float* c, uint2 a0, uint2 a1, uint2 b) {
    asm volatile(
        "mma.sync.aligned.m16n8k8.row.col.f32.tf32.tf32.f32 "
        "{%0,%1,%2,%3}, {%4,%5,%6,%7}, {%8,%9}, {%0,%1,%2,%3};"
        : "+f"(c[0]), "+f"(c[1]), "+f"(c[2]), "+f"(c[3])
        : "r"(a0.x), "r"(a1.x), "r"(a0.y), "r"(a1.y), "r"(b.x), "r"(b.y));
}

// ===================== LayerNorm -> g_Y (tf32, K-permuted) =====================
__global__ void __launch_bounds__(256) ln_kernel(const float* __restrict__ x,
                                                 const float* __restrict__ scale,
                                                 const float* __restrict__ bias) {
    __shared__ float red1[8], red2[8];
    const int row = blockIdx.x;
    const int tid = threadIdx.x, wid = tid >> 5, lid = tid & 31;
    const float* xr = x + (size_t)row * HID;

    float v[8];
#pragma unroll
    for (int i = 0; i < 8; i++) v[i] = xr[tid + i * 256];

    float s1 = 0.f, s2 = 0.f;
#pragma unroll
    for (int i = 0; i < 8; i++) { s1 += v[i]; s2 += v[i] * v[i]; }
#pragma unroll
    for (int o = 16; o > 0; o >>= 1) {
        s1 += __shfl_xor_sync(0xFFFFFFFF, s1, o);
        s2 += __shfl_xor_sync(0xFFFFFFFF, s2, o);
    }
    if (lid == 0) { red1[wid] = s1; red2[wid] = s2; }
    __syncthreads();
    if (tid == 0) {
        float t1 = 0.f, t2 = 0.f;
#pragma unroll
        for (int i = 0; i < 8; i++) { t1 += red1[i]; t2 += red2[i]; }
        red1[0] = t1; red2[0] = t2;
    }
    __syncthreads();
    const float mu  = red1[0] * (1.0f / HID);
    const float var = red2[0] * (1.0f / HID) - mu * mu;
    const float inv = rsqrtf(var + 1e-6f);

    float* yr = g_Y + (size_t)row * HID;
#pragma unroll
    for (int i = 0; i < 8; i++) {
        const int c = tid + i * 256;
        const int pc = (c & ~31) + perm32(c & 31);
        yr[pc] = rna_tf32((v[i] - mu) * inv * scale[c] + bias[c]);
    }
}

// ===================== transpose + tf32 round + K-perm =====================
__global__ void __launch_bounds__(256) transpose_kernel(const float* __restrict__ in,
                                                        float* __restrict__ out,
                                                        int R, int C) {
    __shared__ float t[32][33];
    const int bx = blockIdx.x, by = blockIdx.y;
    const int tx = threadIdx.x, ty = threadIdx.y;   // (32, 8)
    const int x = bx * 32 + tx;
#pragma unroll
    for (int j = 0; j < 32; j += 8)
        t[ty + j][tx] = in[(size_t)(by * 32 + ty + j) * C + x];
    __syncthreads();
    const int oxp = by * 32 + perm32(tx);
#pragma unroll
    for (int j = 0; j < 32; j += 8)
        out[(size_t)(bx * 32 + ty + j) * R + oxp] = rna_tf32(t[tx][ty + j]);
}

// ===================== tiled tf32 mma.sync GEMM =====================
// 256 threads, BM=128, BN=128, BK=32, 8 warps (4m x 2n), warp tile 32x64.
// 2 stages x 40 KB -> 2 CTAs/SM. ALL addresses hoisted: producers carry
// persistent global pointers (+BK/iter) + fixed smem dst bases + stage toggle;
// consumers carry one char* base per operand, everything else is an immediate.
// MODE 0: B = [64 gelu rows | 64 linear rows]; fused GeGLU -> g_Z (64 cols/blk)
// MODE 1: g_Z * W2t -> d_out (128 cols/blk)
#define BM 128
#define BN 128
#define BK 32
#define PADK 40
#define ROW_BYTES (PADK * 4)                   // 160
#define STAGE_ROWS (BM + BN)                   // 256
#define STAGE_BYTES (STAGE_ROWS * ROW_BYTES)   // 40960
#define STAGES 2
#define SMEM_NEED (STAGES * STAGE_BYTES)       // 81920

template <int MODE>
__global__ void __launch_bounds__(256, 2) gemm_kernel(float* __restrict__ outp) {
    constexpr int K  = (MODE == 0) ? HID : IDIM;
    constexpr int NC = K / BK;
    constexpr int numBn = (MODE == 0) ? (IDIM / 64) : (HID / BN);   // 128 / 16

    extern __shared__ float smem[];
    const uint32_t smaddr = smem_u32(smem);

    const int tid = threadIdx.x, wid = tid >> 5, lid = tid & 31;
    const int warp_m = wid & 3;        // 0..3 -> 32-row strip
    const int warp_n = wid >> 2;       // 0..1 -> 64-col strip
    const int g  = lid >> 2;           // 0..7
    const int tg = lid & 3;            // 0..3

    // supertile remap: groups of 8 m-tiles sweep bn together (L2 reuse)
    const int bid   = blockIdx.x;
    const int group = bid / (8 * numBn);
    const int rem   = bid % (8 * numBn);
    const int m0    = (group * 8 + (rem & 7)) * BM;
    const int bn    = rem / 8;

    int nB0, nB1;
    if (MODE == 0) { nB0 = bn * 64;  nB1 = IDIM + bn * 64; }
    else           { nB0 = bn * BN;  nB1 = nB0 + 64; }

    const float* __restrict__ A  = (MODE == 0) ? g_Y : g_Z;
    const float* __restrict__ Bw = (MODE == 0) ? g_W1t : g_W2t;

    // ---- producer state: 8 persistent gmem pointers + 8 fixed smem dst bases
    const int ch = tid & 7;            // 16B chunk in row
    const int pr = tid >> 3;           // 0..31
    const float* gp[8];
    uint32_t dst[8];
    {
        const float* Ag  = A  + (size_t)m0  * K + ch * 4;
        const float* B0g = Bw + (size_t)nB0 * K + ch * 4;
        const float* B1g = Bw + (size_t)nB1 * K + ch * 4;
#pragma unroll
        for (int j = 0; j < 4; ++j) {            // A rows pr + 32j
            gp[j]  = Ag + (size_t)(pr + 32 * j) * K;
            dst[j] = smaddr + (pr + 32 * j) * ROW_BYTES + ch * 16;
        }
#pragma unroll
        for (int j = 0; j < 2; ++j) {            // B0 rows
            gp[4 + j]  = B0g + (size_t)(pr + 32 * j) * K;
            dst[4 + j] = smaddr + (128 + pr + 32 * j) * ROW_BYTES + ch * 16;
        }
#pragma unroll
        for (int j = 0; j < 2; ++j) {            // B1 rows
            gp[6 + j]  = B1g + (size_t)(pr + 32 * j) * K;
            dst[6 + j] = smaddr + (192 + pr + 32 * j) * ROW_BYTES + ch * 16;
        }
    }
    uint32_t psoff = 0;                          // producer stage byte-offset
    auto issue_stage = [&]() {
#pragma unroll
        for (int j = 0; j < 8; ++j) {
            cp_async16(dst[j] + psoff, gp[j]);
            gp[j] += BK;
        }
        cp_commit();
        psoff ^= STAGE_BYTES;
    };

    // ---- consumer fragment bases (per-thread, computed once)
    const char* abase = (const char*)smem + (warp_m * 32 + g) * ROW_BYTES + tg * 8;
    const char* bbase = (const char*)smem + tg * 8 +
        ((MODE == 0) ? (128 + warp_n * 32 + g) : (128 + warp_n * 64 + g)) * ROW_BYTES;

    float acc[2][8][4];
#pragma unroll
    for (int mt = 0; mt < 2; ++mt)
#pragma unroll
        for (int nt = 0; nt < 8; ++nt)
#pragma unroll
            for (int q = 0; q < 4; ++q) acc[mt][nt][q] = 0.f;

    issue_stage();                               // stage 0
    uint32_t csoff = 0;

    for (int c = 0; c < NC; ++c) {
        __syncthreads();
        if (c + 1 < NC) issue_stage(); else cp_commit();
        cp_wait<1>();
        __syncthreads();

        const char* ai = abase + csoff;
        const char* bi = bbase + csoff;
        csoff ^= STAGE_BYTES;

#pragma unroll
        for (int kk = 0; kk < 4; ++kk) {
            uint2 au[2][2];
#pragma unroll
            for (int mt = 0; mt < 2; ++mt) {
                au[mt][0] = *(const uint2*)(ai + mt * 16 * ROW_BYTES + kk * 32);
                au[mt][1] = *(const uint2*)(ai + (mt * 16 + 8) * ROW_BYTES + kk * 32);
            }
            uint2 bu[8];
#pragma unroll
            for (int nt = 0; nt < 8; ++nt) {
                const int ntoff = (MODE == 0)
                    ? ((nt >> 2) * 64 + (nt & 3) * 8) * ROW_BYTES
                    : nt * 8 * ROW_BYTES;
                bu[nt] = *(const uint2*)(bi + ntoff + kk * 32);
            }
#pragma unroll
            for (int mt = 0; mt < 2; ++mt)
#pragma unroll
                for (int nt = 0; nt < 8; ++nt)
                    mma_tf32(acc[mt][nt], au[mt][0], au[mt][1], bu[nt]);
        }
    }

    // ---- epilogue ----
    if (MODE == 0) {
        // z = gelu(left) * right; stored K-permuted into g_Z (64 cols per block).
        const int pp = (tg & 1) * 4 + (tg >> 1);
#pragma unroll
        for (int mt = 0; mt < 2; ++mt) {
            const int r0 = m0 + warp_m * 32 + mt * 16 + g;
#pragma unroll
            for (int nt = 0; nt < 4; ++nt) {
                const int colb = bn * 64 + warp_n * 32 + nt * 8;
                const float* L = acc[mt][nt];       // gelu branch
                const float* R = acc[mt][nt + 4];   // linear branch
                float* z0 = g_Z + (size_t)r0 * IDIM + colb;
                float* z1 = g_Z + (size_t)(r0 + 8) * IDIM + colb;
                z0[pp]     = rna_tf32(gelu_tanh(L[0]) * R[0]);
                z0[pp + 2] = rna_tf32(gelu_tanh(L[1]) * R[1]);
                z1[pp]     = rna_tf32(gelu_tanh(L[2]) * R[2]);
                z1[pp + 2] = rna_tf32(gelu_tanh(L[3]) * R[3]);
            }
        }
    } else {
#pragma unroll
        for (int mt = 0; mt < 2; ++mt) {
            const int r0 = m0 + warp_m * 32 + mt * 16 + g;
#pragma unroll
            for (int nt = 0; nt < 8; ++nt) {
                const int col = nB0 + warp_n * 64 + nt * 8 + tg * 2;
                *(float2*)(outp + (size_t)r0 * HID + col) =
                    make_float2(acc[mt][nt][0], acc[mt][nt][1]);
                *(float2*)(outp + (size_t)(r0 + 8) * HID + col) =
                    make_float2(acc[mt][nt][2], acc[mt][nt][3]);
            }
        }
    }
}

// ===================== launch =====================
extern "C" void kernel_launch(void* const* d_in, const int* in_sizes, int n_in,
                              void* d_out, int out_size) {
    const float* x     = (const float*)d_in[0];
    const float* scale = (const float*)d_in[1];
    const float* bias  = (const float*)d_in[2];
    const float* k1    = (const float*)d_in[3];   // [2048][16384]
    const float* k2    = (const float*)d_in[4];   // [8192][2048]
    float* out = (float*)d_out;

    float* w1t; cudaGetSymbolAddress((void**)&w1t, g_W1t);
    float* w2t; cudaGetSymbolAddress((void**)&w2t, g_W2t);

    cudaFuncSetAttribute(gemm_kernel<0>, cudaFuncAttributeMaxDynamicSharedMemorySize, SMEM_NEED);
    cudaFuncSetAttribute(gemm_kernel<1>, cudaFuncAttributeMaxDynamicSharedMemorySize, SMEM_NEED);

    // 1) LayerNorm -> g_Y (K-permuted tf32)
    ln_kernel<<<TOKENS, 256>>>(x, scale, bias);

    // 2) W1 [2048][16384] -> g_W1t [16384][2048] (K-permuted tf32)
    transpose_kernel<<<dim3(2 * IDIM / 32, HID / 32), dim3(32, 8)>>>(k1, w1t, HID, 2 * IDIM);

    // 3) W2 [8192][2048] -> g_W2t [2048][8192] (K-permuted tf32)
    transpose_kernel<<<dim3(HID / 32, IDIM / 32), dim3(32, 8)>>>(k2, w2t, IDIM, HID);

    // 4) GEMM1 + fused GeGLU -> g_Z   (64 m-tiles x 128 z-col-tiles)
    gemm_kernel<0><<<64 * 128, 256, SMEM_NEED>>>(out);

    // 5) GEMM2 -> out                 (64 m-tiles x 16 n-tiles)
    gemm_kernel<1><<<64 * 16, 256, SMEM_NEED>>>(out);
}